// round 7
// baseline (speedup 1.0000x reference)
#include <cuda_runtime.h>
#include <cstdint>

typedef unsigned long long ull;

#define BB 128
#define SS 1024
#define FF 512
#define HH 32
#define GG 128
#define NTOK (BB*SS)        // 131072

// Scratch (device globals: allocation-free, graph-capturable)
__device__ __align__(16) float g_xg[(size_t)NTOK * GG];  // PERMUTED: [tok][4*j+gate]
__device__ __align__(16) float g_hs[(size_t)NTOK * HH];
__device__ __align__(16) float g_wxp[64 * GG];           // permuted Wx
__device__ __align__(16) float g_blp[GG];                // permuted bl

// ---------------------------------------------------------------------------
// helpers
// ---------------------------------------------------------------------------
__device__ __forceinline__ ull pk2(float lo, float hi) {
    ull r; asm("mov.b64 %0, {%1,%2};" : "=l"(r) : "f"(lo), "f"(hi)); return r;
}
__device__ __forceinline__ void upk2(ull v, float& lo, float& hi) {
    asm("mov.b64 {%0,%1}, %2;" : "=f"(lo), "=f"(hi) : "l"(v));
}
__device__ __forceinline__ void fma2(ull& d, ull a, ull b) {
    asm("fma.rn.f32x2 %0, %1, %2, %0;" : "+l"(d) : "l"(a), "l"(b));
}
__device__ __forceinline__ ull add2(ull a, ull b) {
    ull r; asm("add.rn.f32x2 %0, %1, %2;" : "=l"(r) : "l"(a), "l"(b)); return r;
}

// exact-ish activations (MUFU-based) — used ONLY in the LSTM recurrence
__device__ __forceinline__ float sigf(float x) {
    return __fdividef(1.f, 1.f + __expf(-x));
}
__device__ __forceinline__ float tanhfast(float x) {
    return 2.f * __fdividef(1.f, 1.f + __expf(-2.f * x)) - 1.f;
}

// MUFU-free reciprocal: integer seed + 3 Newton steps (~1e-8 rel for q>0)
__device__ __forceinline__ float rcp_nr(float q) {
    float r = __uint_as_float(0x7EF311C3u - __float_as_uint(q));
    r = r * (2.0f - q * r);
    r = r * (2.0f - q * r);
    r = r * (2.0f - q * r);
    return r;
}
// MUFU-free tanh: Eigen-style rational poly, |err| ~1e-6
__device__ __forceinline__ float tanh_poly(float x) {
    const float cl = 7.90531110763549805f;
    x = fminf(cl, fmaxf(-cl, x));
    float x2 = x * x;
    float p = fmaf(x2, -2.76076847742355e-16f, 2.00018790482477e-13f);
    p = fmaf(x2, p, -8.60467152213735e-11f);
    p = fmaf(x2, p,  5.12229709037114e-08f);
    p = fmaf(x2, p,  1.48572235717979e-05f);
    p = fmaf(x2, p,  6.37261928875436e-04f);
    p = fmaf(x2, p,  4.89352455891786e-03f);
    p = p * x;
    float q = fmaf(x2, 1.19825839466702e-06f, 1.18534705686654e-04f);
    q = fmaf(x2, q, 2.26843463243900e-03f);
    q = fmaf(x2, q, 4.89352518554385e-03f);
    return p * rcp_nr(q);
}

// ---------------------------------------------------------------------------
// K0: permute Wx[64,128] and bl[128] into gate-interleaved layout:
//     wxp[k][4j+g] = Wx[k][32g+j],  blp[4j+g] = bl[32g+j]
// ---------------------------------------------------------------------------
__global__ void k_perm(const float* __restrict__ Wx, const float* __restrict__ bl)
{
    int t = threadIdx.x;          // 0..127  (= 4j+g)
    int j = t >> 2, g = t & 3;
    int kb = blockIdx.x;
    if (kb < 64) g_wxp[kb * GG + t] = Wx[kb * GG + 32 * g + j];
    else         g_blp[t] = bl[32 * g + j];
}

// unrolled 4-k FFMA2 micro-step macros ---------------------------------------
// 4-col weight row (GEMM1 / GEMM3 / W4): accumulate into a0[i],a1[i]
#define ROW4(COMP, WPTR)                                                     \
    { float4 u = *(const float4*)(WPTR);                                     \
      ull w0 = pk2(u.x, u.y), w1 = pk2(u.z, u.w);                            \
      _Pragma("unroll") for (int i = 0; i < 4; i++) {                        \
          ull d = pk2(xv[i].COMP, xv[i].COMP);                               \
          fma2(a0[i], d, w0); fma2(a1[i], d, w1); } }

// 8-col weight row (GEMM2 / W3): accumulate into a[i][0..3]
#define ROW8(COMP, WPTR)                                                     \
    { float4 u0 = *(const float4*)(WPTR);                                    \
      float4 u1 = *(const float4*)((WPTR) + 4);                              \
      ull w0 = pk2(u0.x, u0.y), w1 = pk2(u0.z, u0.w);                        \
      ull w2 = pk2(u1.x, u1.y), w3 = pk2(u1.z, u1.w);                        \
      _Pragma("unroll") for (int i = 0; i < 4; i++) {                        \
          ull d = pk2(xv[i].COMP, xv[i].COMP);                               \
          fma2(a[i][0], d, w0); fma2(a[i][1], d, w1);                        \
          fma2(a[i][2], d, w2); fma2(a[i][3], d, w3); } }

// ---------------------------------------------------------------------------
// K1: front MLP.  xg(permuted) = (tanh(tanh(x@W1+b1)@W2+b2))@Wxp + blp
// CTA: 128 threads, 64 tokens. grid = 2048.
// Thread tile: 4 tokens (tg + {0,16,32,48}) x 4 cols (f32x2 pairs).
// ---------------------------------------------------------------------------
__global__ __launch_bounds__(128) void k_front(
    const float* __restrict__ x,  const float* __restrict__ W1, const float* __restrict__ b1,
    const float* __restrict__ W2, const float* __restrict__ b2)
{
    __shared__ __align__(16) float sa[64 * 68];   // x-chunk, later h2 (stride 68)
    __shared__ __align__(16) float sb[64 * 36];   // h1 (stride 36)

    const int tid  = threadIdx.x;
    const int tok0 = blockIdx.x * 64;
    const int cg   = tid & 7;        // col group
    const int tg   = tid >> 3;       // token group 0..15

    // ---- GEMM1: [64,512] @ [512,32] ----
    {
        ull a0[4], a1[4];
#pragma unroll
        for (int i = 0; i < 4; i++) { a0[i] = 0ull; a1[i] = 0ull; }

        for (int kk = 0; kk < FF; kk += 64) {
            __syncthreads();
#pragma unroll
            for (int q = 0; q < 8; q++) {
                int idx = tid + 128 * q;
                int trow = idx >> 4, kq = idx & 15;
                float4 v = *(const float4*)(x + (size_t)(tok0 + trow) * FF + kk + kq * 4);
                *(float4*)(sa + trow * 68 + kq * 4) = v;
            }
            __syncthreads();
#pragma unroll
            for (int k = 0; k < 64; k += 4) {
                float4 xv[4];
#pragma unroll
                for (int i = 0; i < 4; i++)
                    xv[i] = *(const float4*)(sa + (tg + 16 * i) * 68 + k);
                const float* wp = W1 + (size_t)(kk + k) * 32 + cg * 4;
                ROW4(x, wp);
                ROW4(y, wp + 32);
                ROW4(z, wp + 64);
                ROW4(w, wp + 96);
            }
        }
        float4 bb = *(const float4*)(b1 + cg * 4);
#pragma unroll
        for (int i = 0; i < 4; i++) {
            float v0, v1, v2, v3;
            upk2(a0[i], v0, v1); upk2(a1[i], v2, v3);
            float4 o;
            o.x = tanh_poly(v0 + bb.x); o.y = tanh_poly(v1 + bb.y);
            o.z = tanh_poly(v2 + bb.z); o.w = tanh_poly(v3 + bb.w);
            *(float4*)(sb + (tg + 16 * i) * 36 + cg * 4) = o;
        }
    }
    __syncthreads();

    // ---- GEMM2: [64,32] @ [32,64] -> sa (h2, stride 68) ----
    {
        ull a[4][4];
#pragma unroll
        for (int i = 0; i < 4; i++)
#pragma unroll
            for (int jc = 0; jc < 4; jc++) a[i][jc] = 0ull;

#pragma unroll
        for (int k = 0; k < 32; k += 4) {
            float4 xv[4];
#pragma unroll
            for (int i = 0; i < 4; i++)
                xv[i] = *(const float4*)(sb + (tg + 16 * i) * 36 + k);
            const float* wp = W2 + (size_t)k * 64 + cg * 8;
            ROW8(x, wp);
            ROW8(y, wp + 64);
            ROW8(z, wp + 128);
            ROW8(w, wp + 192);
        }
        float4 c0 = *(const float4*)(b2 + cg * 8);
        float4 c1 = *(const float4*)(b2 + cg * 8 + 4);
#pragma unroll
        for (int i = 0; i < 4; i++) {
            float v[8];
            upk2(a[i][0], v[0], v[1]); upk2(a[i][1], v[2], v[3]);
            upk2(a[i][2], v[4], v[5]); upk2(a[i][3], v[6], v[7]);
            float4 o0, o1;
            o0.x = tanh_poly(v[0] + c0.x); o0.y = tanh_poly(v[1] + c0.y);
            o0.z = tanh_poly(v[2] + c0.z); o0.w = tanh_poly(v[3] + c0.w);
            o1.x = tanh_poly(v[4] + c1.x); o1.y = tanh_poly(v[5] + c1.y);
            o1.z = tanh_poly(v[6] + c1.z); o1.w = tanh_poly(v[7] + c1.w);
            *(float4*)(sa + (tg + 16 * i) * 68 + cg * 8)     = o0;
            *(float4*)(sa + (tg + 16 * i) * 68 + cg * 8 + 4) = o1;
        }
    }
    __syncthreads();

    // ---- GEMM3: [64,64] @ wxp[64,128] + blp -> g_xg (permuted layout) ----
#pragma unroll 1
    for (int cb = 0; cb < 4; cb++) {
        ull a0[4], a1[4];
#pragma unroll
        for (int i = 0; i < 4; i++) { a0[i] = 0ull; a1[i] = 0ull; }
#pragma unroll
        for (int k = 0; k < 64; k += 4) {
            float4 xv[4];
#pragma unroll
            for (int i = 0; i < 4; i++)
                xv[i] = *(const float4*)(sa + (tg + 16 * i) * 68 + k);
            const float* wp = g_wxp + (size_t)k * GG + cb * 32 + cg * 4;
            ROW4(x, wp);
            ROW4(y, wp + GG);
            ROW4(z, wp + 2 * GG);
            ROW4(w, wp + 3 * GG);
        }
        float4 bb = *(const float4*)(g_blp + cb * 32 + cg * 4);
#pragma unroll
        for (int i = 0; i < 4; i++) {
            float v0, v1, v2, v3;
            upk2(a0[i], v0, v1); upk2(a1[i], v2, v3);
            float4 o; o.x = v0 + bb.x; o.y = v1 + bb.y; o.z = v2 + bb.z; o.w = v3 + bb.w;
            *(float4*)(g_xg + (size_t)(tok0 + tg + 16 * i) * GG + cb * 32 + cg * 4) = o;
        }
    }
}

// ---------------------------------------------------------------------------
// K2: LSTM scan. One warp per batch (grid=128, block=32). Thread j = unit j.
// Permuted xg: one LDG.128 per step gives (i,f,g,o) preacts for unit j.
// Prefetch ring depth 4; even/odd-k split f32x2 accumulators.
// ---------------------------------------------------------------------------
__global__ __launch_bounds__(32, 1) void k_lstm(const float* __restrict__ Wh)
{
    const int b = blockIdx.x;
    const int j = threadIdx.x;

    ull wif[HH], wgo[HH];
#pragma unroll
    for (int k = 0; k < HH; k++) {
        const float* row = Wh + k * GG;
        wif[k] = pk2(__ldg(row + j),      __ldg(row + 32 + j));
        wgo[k] = pk2(__ldg(row + 64 + j), __ldg(row + 96 + j));
    }

    const float4* xgb = reinterpret_cast<const float4*>(g_xg) + (size_t)b * SS * 32 + j;
    float* hsb = g_hs + (size_t)b * SS * HH + j;

    float c = 0.f, h = 0.f;
    float4 pf[4];
#pragma unroll
    for (int q = 0; q < 4; q++) pf[q] = __ldg(xgb + (size_t)q * 32);

#pragma unroll 4
    for (int t = 0; t < SS; t++) {
        float4 g4 = pf[t & 3];
        int tn = (t + 4 < SS) ? (t + 4) : (SS - 1);
        pf[t & 3] = __ldg(xgb + (size_t)tn * 32);

        ull aif0 = pk2(g4.x, g4.y), ago0 = pk2(g4.z, g4.w);
        ull aif1 = 0ull, ago1 = 0ull;

#pragma unroll
        for (int k = 0; k < HH; k += 2) {
            float h0 = __shfl_sync(0xffffffffu, h, k);
            float h1 = __shfl_sync(0xffffffffu, h, k + 1);
            ull d0 = pk2(h0, h0), d1 = pk2(h1, h1);
            fma2(aif0, d0, wif[k]);     fma2(ago0, d0, wgo[k]);
            fma2(aif1, d1, wif[k + 1]); fma2(ago1, d1, wgo[k + 1]);
        }
        ull aif = add2(aif0, aif1), ago = add2(ago0, ago1);
        float ai, af, ag, ao;
        upk2(aif, ai, af); upk2(ago, ag, ao);

        float ig = sigf(ai), fg = sigf(af), og = sigf(ao);
        c = fg * c + ig * tanhfast(ag);
        h = og * tanhfast(c);

        hsb[(size_t)t * HH] = h;
    }
}

// ---------------------------------------------------------------------------
// K3: back MLP.  out = tanh(hs@W3+b3) @ W4 + b4
// CTA: 128 threads, 64 tokens. grid = 2048.
// ---------------------------------------------------------------------------
__global__ __launch_bounds__(128) void k_back(
    const float* __restrict__ W3, const float* __restrict__ b3,
    const float* __restrict__ W4, const float* __restrict__ b4,
    float* __restrict__ out)
{
    __shared__ __align__(16) float sa[64 * 68];   // h3 (stride 68)
    __shared__ __align__(16) float sb[64 * 36];   // hs tile (stride 36)

    const int tid  = threadIdx.x;
    const int tok0 = blockIdx.x * 64;
    const int cg   = tid & 7;
    const int tg   = tid >> 3;

    // stage hs tile [64 x 32]
#pragma unroll
    for (int q = 0; q < 4; q++) {
        int idx = tid + 128 * q;
        int trow = idx >> 3, kq = idx & 7;
        float4 v = *(const float4*)(g_hs + (size_t)(tok0 + trow) * HH + kq * 4);
        *(float4*)(sb + trow * 36 + kq * 4) = v;
    }
    __syncthreads();

    // ---- GEMM W3: [64,32] @ [32,64] -> sa ----
    {
        ull a[4][4];
#pragma unroll
        for (int i = 0; i < 4; i++)
#pragma unroll
            for (int jc = 0; jc < 4; jc++) a[i][jc] = 0ull;

#pragma unroll
        for (int k = 0; k < 32; k += 4) {
            float4 xv[4];
#pragma unroll
            for (int i = 0; i < 4; i++)
                xv[i] = *(const float4*)(sb + (tg + 16 * i) * 36 + k);
            const float* wp = W3 + (size_t)k * 64 + cg * 8;
            ROW8(x, wp);
            ROW8(y, wp + 64);
            ROW8(z, wp + 128);
            ROW8(w, wp + 192);
        }
        float4 c0 = *(const float4*)(b3 + cg * 8);
        float4 c1 = *(const float4*)(b3 + cg * 8 + 4);
#pragma unroll
        for (int i = 0; i < 4; i++) {
            float v[8];
            upk2(a[i][0], v[0], v[1]); upk2(a[i][1], v[2], v[3]);
            upk2(a[i][2], v[4], v[5]); upk2(a[i][3], v[6], v[7]);
            float4 o0, o1;
            o0.x = tanh_poly(v[0] + c0.x); o0.y = tanh_poly(v[1] + c0.y);
            o0.z = tanh_poly(v[2] + c0.z); o0.w = tanh_poly(v[3] + c0.w);
            o1.x = tanh_poly(v[4] + c1.x); o1.y = tanh_poly(v[5] + c1.y);
            o1.z = tanh_poly(v[6] + c1.z); o1.w = tanh_poly(v[7] + c1.w);
            *(float4*)(sa + (tg + 16 * i) * 68 + cg * 8)     = o0;
            *(float4*)(sa + (tg + 16 * i) * 68 + cg * 8 + 4) = o1;
        }
    }
    __syncthreads();

    // ---- GEMM W4: [64,64] @ [64,512] + b4 -> out, 16 col-blocks of 32 ----
#pragma unroll 1
    for (int cb = 0; cb < 16; cb++) {
        ull a0[4], a1[4];
#pragma unroll
        for (int i = 0; i < 4; i++) { a0[i] = 0ull; a1[i] = 0ull; }
#pragma unroll
        for (int k = 0; k < 64; k += 4) {
            float4 xv[4];
#pragma unroll
            for (int i = 0; i < 4; i++)
                xv[i] = *(const float4*)(sa + (tg + 16 * i) * 68 + k);
            const float* wp = W4 + (size_t)k * 512 + cb * 32 + cg * 4;
            ROW4(x, wp);
            ROW4(y, wp + 512);
            ROW4(z, wp + 1024);
            ROW4(w, wp + 1536);
        }
        float4 bb = *(const float4*)(b4 + cb * 32 + cg * 4);
#pragma unroll
        for (int i = 0; i < 4; i++) {
            float v0, v1, v2, v3;
            upk2(a0[i], v0, v1); upk2(a1[i], v2, v3);
            float4 o; o.x = v0 + bb.x; o.y = v1 + bb.y; o.z = v2 + bb.z; o.w = v3 + bb.w;
            *(float4*)(out + (size_t)(tok0 + tg + 16 * i) * 512 + cb * 32 + cg * 4) = o;
        }
    }
}

// ---------------------------------------------------------------------------
extern "C" void kernel_launch(void* const* d_in, const int* in_sizes, int n_in,
                              void* d_out, int out_size)
{
    const float* x  = (const float*)d_in[0];
    const float* W1 = (const float*)d_in[1];
    const float* b1 = (const float*)d_in[2];
    const float* W2 = (const float*)d_in[3];
    const float* b2 = (const float*)d_in[4];
    const float* Wx = (const float*)d_in[5];
    const float* Wh = (const float*)d_in[6];
    const float* bl = (const float*)d_in[7];
    const float* W3 = (const float*)d_in[8];
    const float* b3 = (const float*)d_in[9];
    const float* W4 = (const float*)d_in[10];
    const float* b4 = (const float*)d_in[11];
    float* out = (float*)d_out;

    k_perm <<<65, 128>>>(Wx, bl);
    k_front<<<NTOK / 64, 128>>>(x, W1, b1, W2, b2);
    k_lstm <<<BB, 32>>>(Wh);
    k_back <<<NTOK / 64, 128>>>(W3, b3, W4, b4, out);
}

// round 8
// speedup vs baseline: 1.8770x; 1.8770x over previous
#include <cuda_runtime.h>
#include <cstdint>

typedef unsigned long long ull;

// Problem constants
#define BB 128
#define SS 1024
#define FF 512
#define HH 32
#define GG 128              // 4*H
#define NTOK (BB*SS)        // 131072

// Scratch (device globals: allocation-free, graph-capturable)
__device__ __align__(16) float g_xg[(size_t)NTOK * GG];  // PERMUTED: [tok][4*j+gate]
__device__ __align__(16) float g_hs[(size_t)NTOK * HH];
__device__ __align__(16) float g_wxp[64 * GG];           // permuted Wx
__device__ __align__(16) float g_blp[GG];                // permuted bl

// ---------------------------------------------------------------------------
// helpers
// ---------------------------------------------------------------------------
__device__ __forceinline__ ull pk2(float lo, float hi) {
    ull r; asm("mov.b64 %0, {%1,%2};" : "=l"(r) : "f"(lo), "f"(hi)); return r;
}
__device__ __forceinline__ void upk2(ull v, float& lo, float& hi) {
    asm("mov.b64 {%0,%1}, %2;" : "=f"(lo), "=f"(hi) : "l"(v));
}
__device__ __forceinline__ void fma2(ull& d, ull a, ull b) {
    asm("fma.rn.f32x2 %0, %1, %2, %0;" : "+l"(d) : "l"(a), "l"(b));
}
__device__ __forceinline__ ull add2(ull a, ull b) {
    ull r; asm("add.rn.f32x2 %0, %1, %2;" : "=l"(r) : "l"(a), "l"(b)); return r;
}

// MUFU-based activations — used ONLY in the LSTM recurrence (1 warp/SM there)
__device__ __forceinline__ float sigf(float x) {
    return __fdividef(1.f, 1.f + __expf(-x));
}
__device__ __forceinline__ float tanhfast(float x) {
    return 2.f * __fdividef(1.f, 1.f + __expf(-2.f * x)) - 1.f;
}

// MUFU-free reciprocal: integer seed + 3 Newton steps (~1e-7 rel for q>0)
__device__ __forceinline__ float rcp_nr(float q) {
    float r = __uint_as_float(0x7EF311C3u - __float_as_uint(q));
    r = r * (2.0f - q * r);
    r = r * (2.0f - q * r);
    r = r * (2.0f - q * r);
    return r;
}
// MUFU-free tanh: Eigen-style rational poly, |err| ~1e-6, pure fma/alu pipe
__device__ __forceinline__ float tanh_poly(float x) {
    const float cl = 7.90531110763549805f;
    x = fminf(cl, fmaxf(-cl, x));
    float x2 = x * x;
    float p = fmaf(x2, -2.76076847742355e-16f, 2.00018790482477e-13f);
    p = fmaf(x2, p, -8.60467152213735e-11f);
    p = fmaf(x2, p,  5.12229709037114e-08f);
    p = fmaf(x2, p,  1.48572235717979e-05f);
    p = fmaf(x2, p,  6.37261928875436e-04f);
    p = fmaf(x2, p,  4.89352455891786e-03f);
    p = p * x;
    float q = fmaf(x2, 1.19825839466702e-06f, 1.18534705686654e-04f);
    q = fmaf(x2, q, 2.26843463243900e-03f);
    q = fmaf(x2, q, 4.89352518554385e-03f);
    return p * rcp_nr(q);
}

// ---------------------------------------------------------------------------
// K0: permute Wx[64,128] and bl[128] into gate-interleaved layout:
//     wxp[k][4j+g] = Wx[k][32g+j],  blp[4j+g] = bl[32g+j]
// ---------------------------------------------------------------------------
__global__ void k_perm(const float* __restrict__ Wx, const float* __restrict__ bl)
{
    int t = threadIdx.x;          // 0..127  (= 4j+g)
    int j = t >> 2, g = t & 3;
    int kb = blockIdx.x;
    if (kb < 64) g_wxp[kb * GG + t] = Wx[kb * GG + 32 * g + j];
    else         g_blp[t] = bl[32 * g + j];
}

// ---------------------------------------------------------------------------
// K1: front MLP.  xg(permuted) = (tanh(tanh(x@W1+b1)@W2+b2))@wxp + blp
// CTA: 256 threads, 64 tokens.  grid = 2048.  (R1 structure, regs ~90)
// ---------------------------------------------------------------------------
__global__ __launch_bounds__(256) void k_front(
    const float* __restrict__ x,  const float* __restrict__ W1, const float* __restrict__ b1,
    const float* __restrict__ W2, const float* __restrict__ b2)
{
    __shared__ float xs [64 * 68];   // x tile, K-chunk of 64
    __shared__ float h1s[64 * 36];   // tanh(x@W1+b1)
    __shared__ float h2s[64 * 68];   // tanh(h1@W2+b2)

    const int tid  = threadIdx.x;
    const int tok0 = blockIdx.x * 64;

    // ---- GEMM1: [64,512] @ [512,32] ----
    const int c  = tid & 31;
    const int r8 = tid >> 5;
    float acc[8];
#pragma unroll
    for (int i = 0; i < 8; i++) acc[i] = 0.f;

    for (int kk = 0; kk < FF; kk += 64) {
        __syncthreads();
#pragma unroll
        for (int q = 0; q < 4; q++) {
            int idx  = tid + 256 * q;
            int trow = idx >> 4;
            int kq   = idx & 15;
            float4 v = *(const float4*)(x + (size_t)(tok0 + trow) * FF + kk + kq * 4);
            *(float4*)(xs + trow * 68 + kq * 4) = v;
        }
        __syncthreads();
#pragma unroll 4
        for (int k = 0; k < 64; k += 4) {
            float w0 = __ldg(W1 + (kk + k + 0) * 32 + c);
            float w1 = __ldg(W1 + (kk + k + 1) * 32 + c);
            float w2 = __ldg(W1 + (kk + k + 2) * 32 + c);
            float w3 = __ldg(W1 + (kk + k + 3) * 32 + c);
#pragma unroll
            for (int i = 0; i < 8; i++) {
                float4 xv = *(const float4*)(xs + (r8 * 8 + i) * 68 + k);
                acc[i] = fmaf(xv.w, w3, fmaf(xv.z, w2, fmaf(xv.y, w1, fmaf(xv.x, w0, acc[i]))));
            }
        }
    }
    {
        float bb = __ldg(b1 + c);
#pragma unroll
        for (int i = 0; i < 8; i++)
            h1s[(r8 * 8 + i) * 36 + c] = tanh_poly(acc[i] + bb);
    }
    __syncthreads();

    // ---- GEMM2: [64,32] @ [32,64] ----
    {
        const int c2 = tid & 63;
        const int rg = tid >> 6;
        float a2[16];
#pragma unroll
        for (int i = 0; i < 16; i++) a2[i] = 0.f;
#pragma unroll
        for (int k = 0; k < 32; k += 4) {
            float w0 = __ldg(W2 + (k + 0) * 64 + c2);
            float w1 = __ldg(W2 + (k + 1) * 64 + c2);
            float w2 = __ldg(W2 + (k + 2) * 64 + c2);
            float w3 = __ldg(W2 + (k + 3) * 64 + c2);
#pragma unroll
            for (int i = 0; i < 16; i++) {
                float4 xv = *(const float4*)(h1s + (rg * 16 + i) * 36 + k);
                a2[i] = fmaf(xv.w, w3, fmaf(xv.z, w2, fmaf(xv.y, w1, fmaf(xv.x, w0, a2[i]))));
            }
        }
        float bb = __ldg(b2 + c2);
#pragma unroll
        for (int i = 0; i < 16; i++)
            h2s[(rg * 16 + i) * 68 + c2] = tanh_poly(a2[i] + bb);
    }
    __syncthreads();

    // ---- GEMM3: [64,64] @ wxp[64,128] + blp -> g_xg (permuted layout) ----
    {
        const int c3 = tid & 127;
        const int rg = tid >> 7;
        float a3[32];
#pragma unroll
        for (int i = 0; i < 32; i++) a3[i] = 0.f;
#pragma unroll 4
        for (int k = 0; k < 64; k += 4) {
            float w0 = g_wxp[(k + 0) * GG + c3];
            float w1 = g_wxp[(k + 1) * GG + c3];
            float w2 = g_wxp[(k + 2) * GG + c3];
            float w3 = g_wxp[(k + 3) * GG + c3];
#pragma unroll
            for (int i = 0; i < 32; i++) {
                float4 xv = *(const float4*)(h2s + (rg * 32 + i) * 68 + k);
                a3[i] = fmaf(xv.w, w3, fmaf(xv.z, w2, fmaf(xv.y, w1, fmaf(xv.x, w0, a3[i]))));
            }
        }
        float bb = g_blp[c3];
#pragma unroll
        for (int i = 0; i < 32; i++)
            g_xg[(size_t)(tok0 + rg * 32 + i) * GG + c3] = a3[i] + bb;
    }
}

// ---------------------------------------------------------------------------
// K2: LSTM scan. One warp per batch (grid=128, block=32). Thread j = unit j.
// Permuted xg: one LDG.128 per step gives (i,f,g,o) preacts for unit j.
// Prefetch ring depth 4; even/odd-k split f32x2 accumulator chains.
// ---------------------------------------------------------------------------
__global__ __launch_bounds__(32, 1) void k_lstm(const float* __restrict__ Wh)
{
    const int b = blockIdx.x;
    const int j = threadIdx.x;

    ull wif[HH], wgo[HH];
#pragma unroll
    for (int k = 0; k < HH; k++) {
        const float* row = Wh + k * GG;
        wif[k] = pk2(__ldg(row + j),      __ldg(row + 32 + j));
        wgo[k] = pk2(__ldg(row + 64 + j), __ldg(row + 96 + j));
    }

    const float4* xgb = reinterpret_cast<const float4*>(g_xg) + (size_t)b * SS * 32 + j;
    float* hsb = g_hs + (size_t)b * SS * HH + j;

    float c = 0.f, h = 0.f;
    float4 pf[4];
#pragma unroll
    for (int q = 0; q < 4; q++) pf[q] = __ldg(xgb + (size_t)q * 32);

#pragma unroll 4
    for (int t = 0; t < SS; t++) {
        float4 g4 = pf[t & 3];
        int tn = (t + 4 < SS) ? (t + 4) : (SS - 1);
        pf[t & 3] = __ldg(xgb + (size_t)tn * 32);

        ull aif0 = pk2(g4.x, g4.y), ago0 = pk2(g4.z, g4.w);
        ull aif1 = 0ull, ago1 = 0ull;

#pragma unroll
        for (int k = 0; k < HH; k += 2) {
            float h0 = __shfl_sync(0xffffffffu, h, k);
            float h1 = __shfl_sync(0xffffffffu, h, k + 1);
            ull d0 = pk2(h0, h0), d1 = pk2(h1, h1);
            fma2(aif0, d0, wif[k]);     fma2(ago0, d0, wgo[k]);
            fma2(aif1, d1, wif[k + 1]); fma2(ago1, d1, wgo[k + 1]);
        }
        ull aif = add2(aif0, aif1), ago = add2(ago0, ago1);
        float ai, af, ag, ao;
        upk2(aif, ai, af); upk2(ago, ag, ao);

        float ig = sigf(ai), fg = sigf(af), og = sigf(ao);
        c = fg * c + ig * tanhfast(ag);
        h = og * tanhfast(c);

        hsb[(size_t)t * HH] = h;
    }
}

// ---------------------------------------------------------------------------
// K3: back MLP.  out = tanh(hs@W3+b3) @ W4 + b4
// CTA: 256 threads, 64 tokens. grid = 2048.  (R1 structure)
// ---------------------------------------------------------------------------
__global__ __launch_bounds__(256) void k_back(
    const float* __restrict__ W3, const float* __restrict__ b3,
    const float* __restrict__ W4, const float* __restrict__ b4,
    float* __restrict__ out)
{
    __shared__ float hss[64 * 36];
    __shared__ float h3s[64 * 68];

    const int tid  = threadIdx.x;
    const int tok0 = blockIdx.x * 64;

    // stage hs tile (64x32)
#pragma unroll
    for (int q = 0; q < 2; q++) {
        int idx = tid + 256 * q;          // 0..511
        int trow = idx >> 3, kq = idx & 7;
        float4 v = *(const float4*)(g_hs + (size_t)(tok0 + trow) * HH + kq * 4);
        *(float4*)(hss + trow * 36 + kq * 4) = v;
    }
    __syncthreads();

    // ---- GEMM W3: [64,32]@[32,64] ----
    {
        const int c2 = tid & 63;
        const int rg = tid >> 6;
        float a2[16];
#pragma unroll
        for (int i = 0; i < 16; i++) a2[i] = 0.f;
#pragma unroll
        for (int k = 0; k < 32; k += 4) {
            float w0 = __ldg(W3 + (k + 0) * 64 + c2);
            float w1 = __ldg(W3 + (k + 1) * 64 + c2);
            float w2 = __ldg(W3 + (k + 2) * 64 + c2);
            float w3 = __ldg(W3 + (k + 3) * 64 + c2);
#pragma unroll
            for (int i = 0; i < 16; i++) {
                float4 xv = *(const float4*)(hss + (rg * 16 + i) * 36 + k);
                a2[i] = fmaf(xv.w, w3, fmaf(xv.z, w2, fmaf(xv.y, w1, fmaf(xv.x, w0, a2[i]))));
            }
        }
        float bb = __ldg(b3 + c2);
#pragma unroll
        for (int i = 0; i < 16; i++)
            h3s[(rg * 16 + i) * 68 + c2] = tanh_poly(a2[i] + bb);
    }
    __syncthreads();

    // ---- GEMM W4: [64,64]@[64,512], N-chunks of 128 ----
    const int c4 = tid & 127;
    const int rg = tid >> 7;
    for (int nc = 0; nc < 512; nc += 128) {
        float a4[32];
#pragma unroll
        for (int i = 0; i < 32; i++) a4[i] = 0.f;
#pragma unroll 4
        for (int k = 0; k < 64; k += 4) {
            float w0 = __ldg(W4 + (k + 0) * 512 + nc + c4);
            float w1 = __ldg(W4 + (k + 1) * 512 + nc + c4);
            float w2 = __ldg(W4 + (k + 2) * 512 + nc + c4);
            float w3 = __ldg(W4 + (k + 3) * 512 + nc + c4);
#pragma unroll
            for (int i = 0; i < 32; i++) {
                float4 xv = *(const float4*)(h3s + (rg * 32 + i) * 68 + k);
                a4[i] = fmaf(xv.w, w3, fmaf(xv.z, w2, fmaf(xv.y, w1, fmaf(xv.x, w0, a4[i]))));
            }
        }
        float bb = __ldg(b4 + nc + c4);
#pragma unroll
        for (int i = 0; i < 32; i++)
            out[(size_t)(tok0 + rg * 32 + i) * 512 + nc + c4] = a4[i] + bb;
    }
}

// ---------------------------------------------------------------------------
extern "C" void kernel_launch(void* const* d_in, const int* in_sizes, int n_in,
                              void* d_out, int out_size)
{
    const float* x  = (const float*)d_in[0];
    const float* W1 = (const float*)d_in[1];
    const float* b1 = (const float*)d_in[2];
    const float* W2 = (const float*)d_in[3];
    const float* b2 = (const float*)d_in[4];
    const float* Wx = (const float*)d_in[5];
    const float* Wh = (const float*)d_in[6];
    const float* bl = (const float*)d_in[7];
    const float* W3 = (const float*)d_in[8];
    const float* b3 = (const float*)d_in[9];
    const float* W4 = (const float*)d_in[10];
    const float* b4 = (const float*)d_in[11];
    float* out = (float*)d_out;

    k_perm <<<65, 128>>>(Wx, bl);
    k_front<<<NTOK / 64, 256>>>(x, W1, b1, W2, b2);
    k_lstm <<<BB, 32>>>(Wh);
    k_back <<<NTOK / 64, 256>>>(W3, b3, W4, b4, out);
}